// round 14
// baseline (speedup 1.0000x reference)
#include <cuda_runtime.h>
#include <cuda_bf16.h>

// LocalPatternExtractor: binary-weight dw-conv -> binary pw-conv -> BN -> 4-step
// quantized LIF. Forward-value analysis: quantize_pot_ste clips the membrane
// potential to round(v/step) in [-128,127] with step = 1/128, so quantized mem
// is <= 127/128 < THRESHOLD = 1.0; the spike forward value is the hard
// comparison (mem >= THRESHOLD) on that quantized mem (sigmoid surrogate is
// forward-canceled by the stop_gradient STE). No spike ever fires: out == 0
// everywhere, reg_loss = 0.01 * mean(0) = 0. Kernel job: write out_size float
// zeros over the 0xAA-poisoned d_out.
//
// Evidence trail (closed problem):
// R4:  fused tail kernel away (16.9 -> 14.8 us total, kernel 13.6 us).
// R7:  persistent grid-stride, occ 26%->56%: kernel time unchanged.
// R8:  cudaMemsetAsync driver fill: total identical => path-independent
//      LTS write-port ceiling (stores cannot bypass LTS; TMA shares cap).
// R9:  st.global.v8.f32: kernel 13.6 -> 13.2 us.
// R10/11: fewer CTAs (512/1024-thr blocks): kernel 12.74 -> 12.67 us,
//      saturated. Device time = 81.9 MB / 6.45 TB/s = the measured LTS
//      chip cap (~6300 B/cyc) at NAT clocks. Total pinned at ~14.8 us
//      harness replay/timing floor (gap grew 1.2 -> 2.1 us as kernel
//      shrank). Both floors confirmed from independent directions.
// R13: final probe — .cs (evict-first) store policy, the only untouched
//      knob. Cannot raise the write-port rate; predicted neutral. This
//      structure (2501 x 1024, one 256-bit store/thread, fused tail) is
//      the final configuration either way.

__global__ void __launch_bounds__(1024) lpe_zero_v8(float* __restrict__ out,
                                                    long long n) {
    // One 256-bit streaming store (8 floats, 32 B) per thread; warp = 1 KB.
    long long i8 = ((long long)blockIdx.x * blockDim.x + threadIdx.x) << 3;
    if (i8 + 7 < n) {
        asm volatile(
            "st.global.cs.v8.f32 [%0], {%1,%1,%1,%1,%1,%1,%1,%1};"
            :: "l"(out + i8), "f"(0.0f) : "memory");
    } else if (i8 < n) {
        // Straddling thread: scalar tail (at most 7 elements), same node.
        for (long long j = i8; j < n; ++j) out[j] = 0.f;
    }
}

extern "C" void kernel_launch(void* const* d_in, const int* in_sizes, int n_in,
                              void* d_out, int out_size) {
    (void)d_in; (void)in_sizes; (void)n_in;

    long long n        = (long long)out_size;      // 20,480,001 floats
    long long nthreads = (n + 7) >> 3;             // one 32B store per thread
    const int threads  = 1024;
    long long blocks   = (nthreads + threads - 1) / threads;  // 2501

    lpe_zero_v8<<<(unsigned)blocks, threads>>>((float*)d_out, n);
}